// round 15
// baseline (speedup 1.0000x reference)
#include <cuda_runtime.h>
#include <cuda_fp16.h>
#include <stdint.h>

#define N_NODES     50000
#define IN_DIM      128
#define N_EDGES     500000
#define EDGE_UNITS  (N_EDGES / 2)          // 250000 int2-edge units
#define NG4         (N_NODES / 4)          // 12500 groups of 4 nodes
#define PROJ_THREADS 512                   // <=512 thr -> edge CTA co-resident
#define EDGE_CTAS    96
#define EDGE_THREADS 1024
#define EDGE_SLOTS   3                     // 3*98304 >= 250000
#define TABLE_BYTES  (N_NODES * 4)         // 195.3 KB of half2 pairs
#define TABLE_VEC16  (TABLE_BYTES / 16)    // 12500 16B chunks

// Packed per-node projections: g_pair[n] = (proj_src[n], proj_dst[n]) as half2.
__device__ __half2 g_pair[N_NODES];

// ---------------------------------------------------------------------------
// Kernel 1: persistent node projection, 512 threads/CTA so an edge CTA
// (1024 thr + 195KB smem) fits on the SAME SM: 1536 thr, ~61K regs.
// Triggers PDL at entry -> edge launches and prefetches concurrently.
// Grid-stride, 4 nodes/warp; half2-packed 16B stores.
// ---------------------------------------------------------------------------
__global__ __launch_bounds__(PROJ_THREADS, 1)
void proj_kernel(const float* __restrict__ x, const float* __restrict__ W) {
    cudaTriggerProgrammaticLaunchCompletion();   // all CTAs enter in wave 1

    const int tid  = threadIdx.x;
    const int wid  = tid >> 5;
    const int lane = tid & 31;
    const int nwarps      = gridDim.x * (PROJ_THREADS / 32);
    const int warp_global = blockIdx.x * (PROJ_THREADS / 32) + wid;

    const float4 wa = reinterpret_cast<const float4*>(W)[lane];            // W[:128]
    const float4 wb = reinterpret_cast<const float4*>(W + IN_DIM)[lane];   // W[128:]

    for (int g = warp_global; g < NG4; g += nwarps) {
        const int base = g * 4;
        float4 xv[4];
        #pragma unroll
        for (int i = 0; i < 4; i++)
            xv[i] = reinterpret_cast<const float4*>(x + (size_t)(base + i) * IN_DIM)[lane];

        float sa[4], sb[4];
        #pragma unroll
        for (int i = 0; i < 4; i++) {
            sa[i] = xv[i].x * wa.x + xv[i].y * wa.y + xv[i].z * wa.z + xv[i].w * wa.w;
            sb[i] = xv[i].x * wb.x + xv[i].y * wb.y + xv[i].z * wb.z + xv[i].w * wb.w;
        }
        #pragma unroll
        for (int off = 16; off > 0; off >>= 1) {
            #pragma unroll
            for (int i = 0; i < 4; i++) {
                sa[i] += __shfl_xor_sync(0xFFFFFFFFu, sa[i], off);
                sb[i] += __shfl_xor_sync(0xFFFFFFFFu, sb[i], off);
            }
        }
        if (lane == 0) {
            __half2 p[4];
            #pragma unroll
            for (int i = 0; i < 4; i++) p[i] = __floats2half2_rn(sa[i], sb[i]);
            *reinterpret_cast<uint4*>(g_pair + base) = *reinterpret_cast<uint4*>(p);
        }
    }
}

// ---------------------------------------------------------------------------
// Sigmoid with one MUFU op: sigmoid(x) = 0.5*tanh(x/2) + 0.5
// ---------------------------------------------------------------------------
__device__ __forceinline__ float sigmoid_tanh(float v) {
    float t;
    asm("tanh.approx.f32 %0, %1;" : "=f"(t) : "f"(0.5f * v));
    return fmaf(0.5f, t, 0.5f);
}

__device__ __forceinline__ void cp_async16(uint32_t smem_dst, const void* gmem_src) {
    asm volatile("cp.async.cg.shared.global [%0], [%1], 16;"
                 :: "r"(smem_dst), "l"(gmem_src));
}

// ---------------------------------------------------------------------------
// Kernel 2 (PDL secondary): co-resident with proj from ~t=0. Prefetches the
// whole edge stream into registers (TRUE overlap with proj's 25.6MB read),
// waits on the grid dependency, stages the 195KB table via cp.async, then
// LDS gathers + tanh + STG. Serial tail after proj: ~staging+gather only.
// ---------------------------------------------------------------------------
__global__ __launch_bounds__(EDGE_THREADS, 1)
void edge_kernel(const int* __restrict__ edge_index,
                 const float* __restrict__ edge_weight,
                 const float* __restrict__ b,
                 float* __restrict__ out) {
    extern __shared__ __half2 s_tab[];   // 195.3 KB table

    const int tid = threadIdx.x;

    // --- Independent work: prefetch edge stream (concurrent with proj) ---
    const int t0     = blockIdx.x * EDGE_THREADS + tid;
    const int stride = EDGE_CTAS * EDGE_THREADS;          // 98304
    int2 sv[EDGE_SLOTS], dv[EDGE_SLOTS]; float2 wv[EDGE_SLOTS];
    #pragma unroll
    for (int s = 0; s < EDGE_SLOTS; s++) {
        const int t = t0 + s * stride;
        if (t < EDGE_UNITS) {
            sv[s] = reinterpret_cast<const int2*>(edge_index)[t];
            dv[s] = reinterpret_cast<const int2*>(edge_index + N_EDGES)[t];
            wv[s] = reinterpret_cast<const float2*>(edge_weight)[t];
        }
    }
    const float bias = b[0];

    // --- Dependency point: proj's g_pair writes must be visible ---
    cudaGridDependencySynchronize();

    // --- Stage the table: 12500 x cp.async.cg 16B, fully coalesced ---
    {
        uint32_t s_base = (uint32_t)__cvta_generic_to_shared(s_tab);
        const char* g_base = reinterpret_cast<const char*>(g_pair);
        for (int i = tid; i < TABLE_VEC16; i += EDGE_THREADS)
            cp_async16(s_base + i * 16, g_base + i * 16);
        asm volatile("cp.async.commit_group;");
        asm volatile("cp.async.wait_group 0;");
    }
    __syncthreads();

    // --- Gather + sigmoid + scale (operands already in regs/smem) ---
    #pragma unroll
    for (int s = 0; s < EDGE_SLOTS; s++) {
        const int t = t0 + s * stride;
        if (t < EDGE_UNITS) {
            const int i0 = min(max(sv[s].x, 0), N_NODES - 1);
            const int i1 = min(max(sv[s].y, 0), N_NODES - 1);
            const int j0 = min(max(dv[s].x, 0), N_NODES - 1);
            const int j1 = min(max(dv[s].y, 0), N_NODES - 1);

            const float ps0 = __low2float(s_tab[i0]),  ps1 = __low2float(s_tab[i1]);
            const float pd0 = __high2float(s_tab[j0]), pd1 = __high2float(s_tab[j1]);

            float2 r;
            r.x = wv[s].x * sigmoid_tanh(ps0 + pd0 + bias);
            r.y = wv[s].y * sigmoid_tanh(ps1 + pd1 + bias);
            reinterpret_cast<float2*>(out)[t] = r;
        }
    }
}

// ---------------------------------------------------------------------------
// Launch. Inputs (metadata order): x, edge_index, edge_weight, W, b.
// proj: one wave of 512-thread CTAs (leaves room for edge CTAs).
// edge: PDL secondary, co-resident from the start.
// ---------------------------------------------------------------------------
extern "C" void kernel_launch(void* const* d_in, const int* in_sizes, int n_in,
                              void* d_out, int out_size) {
    const float* x  = (const float*)d_in[0];
    const int*   ei = (const int*)d_in[1];
    const float* ew = (const float*)d_in[2];
    const float* W  = (const float*)d_in[3];
    const float* b  = (const float*)d_in[4];
    float*       o  = (float*)d_out;

    cudaFuncSetAttribute(edge_kernel,
                         cudaFuncAttributeMaxDynamicSharedMemorySize, TABLE_BYTES);

    int dev = 0, sms = 148;
    cudaGetDevice(&dev);
    cudaDeviceGetAttribute(&sms, cudaDevAttrMultiProcessorCount, dev);

    // Kernel 1: persistent proj, one wave, 512 threads/CTA
    proj_kernel<<<sms, PROJ_THREADS>>>(x, W);

    // Kernel 2: PDL secondary — starts while proj is running (co-resident)
    {
        cudaLaunchConfig_t cfg = {};
        cfg.gridDim          = dim3(EDGE_CTAS, 1, 1);
        cfg.blockDim         = dim3(EDGE_THREADS, 1, 1);
        cfg.dynamicSmemBytes = TABLE_BYTES;
        cfg.stream           = 0;
        cudaLaunchAttribute at[1];
        at[0].id = cudaLaunchAttributeProgrammaticStreamSerialization;
        at[0].val.programmaticStreamSerializationAllowed = 1;
        cfg.attrs    = at;
        cfg.numAttrs = 1;
        cudaLaunchKernelEx(&cfg, edge_kernel, ei, ew, b, o);
    }
}